// round 17
// baseline (speedup 1.0000x reference)
#include <cuda_runtime.h>
#include <cuda_bf16.h>

// Problem constants (reference: B=32, A=4096, P=8388608, E=8)
#define Bn 32
#define An 4096
#define En 8

#define PT 256
#define ENG_BLK Bn                  // blocks 0..31: engmax publishers
#define PAIR_BLK 64                 // blocks 32..95: pair publishers
#define WAIT_BID (ENG_BLK + PAIR_BLK)   // block 96: the waiter
#define NBLK (WAIT_BID + 1)         // 97 blocks (all co-resident: < 148 SMs)
#define WPB (PT / 32)               // 8 warps/block
#define NPW (PAIR_BLK * WPB)        // 512 pair warps
#define PREFIX (NPW * 32)           // 16384 pairs in stage A (1 per lane)
#define ARRIVALS (NPW + ENG_BLK)    // 544 rendezvous arrivals
#define WTILE 128                   // fallback tile

// Device state. Zero at module load; the waiter resets both after all 544
// arrivals (i.e., after every publisher's last memory action), so each
// graph replay starts clean.
__device__ unsigned g_done;    // resolved bits: eng_big | too_close
__device__ unsigned g_ready;   // publisher arrivals

__device__ __forceinline__ unsigned poll_u32(const unsigned* p) {
    unsigned v;
    asm volatile("ld.global.cg.u32 %0, [%1];" : "=r"(v) : "l"(p) : "memory");
    return v;
}

// Exact pair test; returns (1u<<n) if too close, else 0.
__device__ __forceinline__ unsigned pair_bit(const float* __restrict__ pos,
                                             const int* __restrict__ elm,
                                             const float* s_rad,
                                             int nb, int i, int j) {
    int ai = nb * An + i;
    int aj = nb * An + j;
    float ax = __ldg(pos + 3 * ai + 0);
    float ay = __ldg(pos + 3 * ai + 1);
    float az = __ldg(pos + 3 * ai + 2);
    float bx = __ldg(pos + 3 * aj + 0);
    float by = __ldg(pos + 3 * aj + 1);
    float bz = __ldg(pos + 3 * aj + 2);
    float rs = s_rad[__ldg(elm + ai) & 7] + s_rad[__ldg(elm + aj) & 7];
    float dx = bx - ax, dy = by - ay, dz = bz - az;
    float sod = dx * dx + dy * dy + dz * dz;
    return (rs * rs >= sod) ? (1u << nb) : 0u;
}

// ---------------------------------------------------------------------------
// ONE kernel node. Publishers (96 blocks) RED bits into g_done, fence
// (publisher threads only), add to g_ready, and EXIT — they never wait.
// The dedicated waiter block spins on g_ready==544, then alone writes the
// entire float32 output and resets state. Fence-between-OR-and-ADD makes
// ready==544 imply full mask visibility (protocol proven in R9).
__global__ void __launch_bounds__(PT)
k_all(const float* __restrict__ pos,
      const float* __restrict__ eng,
      const int* __restrict__ elm,
      const float* __restrict__ radius,
      const float* __restrict__ eng_atm,
      const int* __restrict__ nn,
      const int* __restrict__ ii,
      const int* __restrict__ jj,
      int P,
      float* __restrict__ out, int out_size) {
    const int tid  = threadIdx.x;
    const int bid  = blockIdx.x;
    const int lane = tid & 31;
    const int wid  = tid >> 5;

    if (bid < ENG_BLK) {
        // ---- engmax publisher for structure `bid` ----
        __shared__ float s_atm[En];
        __shared__ float s_red[PT / 32];
        if (tid < En) s_atm[tid] = eng_atm[tid];
        __syncthreads();

        const int4* row = (const int4*)(elm + bid * An);
        float s = 0.f;
        #pragma unroll
        for (int t = 0; t < An / (PT * 4); ++t) {     // 4 int4 per thread
            int4 e4 = __ldg(row + tid + t * PT);
            s += s_atm[e4.x & 7] + s_atm[e4.y & 7]
               + s_atm[e4.z & 7] + s_atm[e4.w & 7];
        }
        #pragma unroll
        for (int o = 16; o > 0; o >>= 1)
            s += __shfl_down_sync(0xFFFFFFFFu, s, o);
        if ((tid & 31) == 0) s_red[tid >> 5] = s;
        __syncthreads();
        if (tid == 0) {
            float tot = 0.f;
            #pragma unroll
            for (int w = 0; w < PT / 32; ++w) tot += s_red[w];
            if (__ldg(eng + bid) >= tot)
                atomicOr(&g_done, 1u << bid);
            __threadfence();                  // order OR before arrival
            atomicAdd(&g_ready, 1u);
        }
        return;                               // publisher exits
    }

    if (bid < WAIT_BID) {
        // ---- pair publisher: one pair per lane over the shared prefix ----
        __shared__ float s_rad[En];
        if (tid < En) s_rad[tid] = radius[tid];
        __syncthreads();

        const int gw = (bid - ENG_BLK) * WPB + wid;
        int q = gw * 32 + lane;
        unsigned local = 0u;
        if (q < P)
            local = pair_bit(pos, elm, s_rad, __ldg(nn + q),
                             __ldg(ii + q), __ldg(jj + q));
        unsigned wbits = __reduce_or_sync(0xFFFFFFFFu, local);
        if (lane == 0) {
            if (wbits) atomicOr(&g_done, wbits);
            __threadfence();                  // order OR before arrival
            atomicAdd(&g_ready, 1u);          // unconditional (fixed count)
        }
        return;                               // publisher exits
    }

    // ======================= WAITER BLOCK =======================
    __shared__ unsigned s_m;
    __shared__ float s_rad[En];
    if (tid < En) s_rad[tid] = radius[tid];

    if (tid == 0) {
        // Terminates: all 97 blocks co-resident; publishers never wait.
        while (poll_u32(&g_ready) < ARRIVALS) { }
        __threadfence();                      // acquire side
        s_m = poll_u32(&g_done);
    }
    __syncthreads();
    unsigned m = s_m;

    if (m != 0xFFFFFFFFu) {
        // ---- exact fallback (statistically never): scan [PREFIX, P) ----
        const long long ntiles =
            ((long long)P - PREFIX + WTILE - 1) / WTILE;
        for (long long t = wid; t < ntiles; t += WPB) {
            m = s_m;
            if (m == 0xFFFFFFFFu) break;
            long long idx = (long long)PREFIX + t * WTILE + lane * 4;
            unsigned local = 0u;
            if (idx + 4 <= (long long)P) {
                int4 n4 = __ldg((const int4*)(nn + idx));
                int4 i4 = __ldg((const int4*)(ii + idx));
                int4 j4 = __ldg((const int4*)(jj + idx));
                int na[4] = {n4.x, n4.y, n4.z, n4.w};
                int ia[4] = {i4.x, i4.y, i4.z, i4.w};
                int ja[4] = {j4.x, j4.y, j4.z, j4.w};
                #pragma unroll
                for (int k = 0; k < 4; ++k)
                    if (!((m >> na[k]) & 1u))
                        local |= pair_bit(pos, elm, s_rad,
                                          na[k], ia[k], ja[k]);
            } else if (idx < (long long)P) {
                for (int k = 0; k < 4; ++k) {
                    long long q = idx + k;
                    if (q >= (long long)P) break;
                    int nb = __ldg(nn + q);
                    if (!((m >> nb) & 1u))
                        local |= pair_bit(pos, elm, s_rad, nb,
                                          __ldg(ii + q), __ldg(jj + q));
                }
            }
            unsigned wbits = __reduce_or_sync(0xFFFFFFFFu, local) & ~m;
            if (wbits && lane == 0) atomicOr(&s_m, wbits);
        }
        __syncthreads();
        m = s_m;
    }

    // ---- sole writer of the output (zeros included: no memset node) ----
    for (int b = tid; b < out_size; b += PT)
        out[b] = (b < Bn) ? (float)((m >> b) & 1u) : 0.0f;
    __syncthreads();
    if (tid == 0) { g_ready = 0u; g_done = 0u; }  // clean for next replay
}

// ---------------------------------------------------------------------------
// Inputs (metadata order): pos[B,A,3] f32, eng[B] f32, elm[B,A] i32,
// radius[E] f32, eng_atm[E] f32, n[P] i32, i[P] i32, j[P] i32.
// Output: float32[B] (0.0 / 1.0).
// ONE graph node. Publishers never wait; exactly one block waits; single
// writer for every output element.
extern "C" void kernel_launch(void* const* d_in, const int* in_sizes, int n_in,
                              void* d_out, int out_size) {
    const float* pos     = (const float*)d_in[0];
    const float* eng     = (const float*)d_in[1];
    const int*   elm     = (const int*)d_in[2];
    const float* radius  = (const float*)d_in[3];
    const float* eng_atm = (const float*)d_in[4];
    const int*   nn      = (const int*)d_in[5];
    const int*   ii      = (const int*)d_in[6];
    const int*   jj      = (const int*)d_in[7];
    int P = in_sizes[5];

    k_all<<<NBLK, PT>>>(pos, eng, elm, radius, eng_atm, nn, ii, jj, P,
                        (float*)d_out, out_size);
}